// round 4
// baseline (speedup 1.0000x reference)
#include <cuda_runtime.h>
#include <cuda_bf16.h>
#include <cstdint>

// FPQuantizer: per-row absmax clip is the identity, so the reference reduces
// to a pure elementwise flex-fp8 quantizer:
//   bias = 7.15625 (exact bf16)
//   L    = max(floor(log2|x| + bias), 1)
//   s    = 2^(L-12) * 2^(-0.15625)
//   out  = rint(x / s) * s
// Transcendental-free via exponent-field bit tricks:
//   floor(log2|x| + 7.15625) = e + 7 + (mant >= 2^0.84375)
//
// R4: MLP=8 per thread (8x float4, 128B), block-strided lane-contiguous
// addressing (every LDG.128/STG.128 fully coalesced), all 8 loads
// front-batched. R3 (MLP=4) reached 79.5% DRAM; latency term still partially
// exposed -> double in-flight bytes per thread.

#define QT_THRESH 1.79470907f   // 2^0.84375, fp32-rounded
#define QT_C      0.89735454f   // 2^(-0.15625)
#define QT_CINV   1.11438674f   // 2^(+0.15625)

__device__ __forceinline__ float fpq_quantize(float x) {
    uint32_t b = __float_as_uint(x) & 0x7fffffffu;
    int e = (int)(b >> 23) - 127;
    float mant = __uint_as_float((b & 0x7fffffu) | 0x3f800000u);
    int L = e + 7 + (mant >= QT_THRESH ? 1 : 0);
    L = (L < 1) ? 1 : L;                       // x==0 -> L clamped to 1 -> out 0. Matches ref.
    int k = L - 12;
    float p    = __uint_as_float((uint32_t)(k + 127) << 23);
    float pinv = __uint_as_float((uint32_t)(127 - k) << 23);
    return rintf(x * (pinv * QT_CINV)) * (p * QT_C);  // round-half-even == jnp.round
}

__device__ __forceinline__ float4 fpq_quantize4(float4 v) {
    float4 q;
    q.x = fpq_quantize(v.x);
    q.y = fpq_quantize(v.y);
    q.z = fpq_quantize(v.z);
    q.w = fpq_quantize(v.w);
    return q;
}

#define VPT 8   // float4 vectors per thread

// Block processes VPT*blockDim float4s; thread t handles t + k*256 within the
// block tile — every memory instruction is warp-contiguous (512B/warp).
__global__ __launch_bounds__(256) void FPQuantizer_76312978915927_kernel(
    const float4* __restrict__ x, float4* __restrict__ out, int n4)
{
    const int T = 256;
    int base = blockIdx.x * (T * VPT) + threadIdx.x;

    if (base + (VPT - 1) * T < n4) {
        float4 v[VPT];
        // front-batch all VPT independent, fully-coalesced loads (MLP=VPT)
        #pragma unroll
        for (int k = 0; k < VPT; ++k) v[k] = __ldcs(x + base + k * T);
        #pragma unroll
        for (int k = 0; k < VPT; ++k) __stcs(out + base + k * T, fpq_quantize4(v[k]));
    } else {
        // ragged tail block (not hit for 8192x8192: 16M float4s / 2048 exact)
        #pragma unroll
        for (int k = 0; k < VPT; ++k) {
            int i = base + k * T;
            if (i < n4) __stcs(out + i, fpq_quantize4(__ldcs(x + i)));
        }
    }
}

// Scalar tail kernel (defensive; n divisible by 4 here so it won't launch)
__global__ void FPQuantizer_tail_kernel(const float* __restrict__ x,
                                        float* __restrict__ out,
                                        int start, int n)
{
    int i = start + blockIdx.x * blockDim.x + threadIdx.x;
    if (i < n) out[i] = fpq_quantize(x[i]);
}

extern "C" void kernel_launch(void* const* d_in, const int* in_sizes, int n_in,
                              void* d_out, int out_size)
{
    const float* x = (const float*)d_in[0];
    float* out = (float*)d_out;

    int n = out_size;
    int n4 = n >> 2;                       // number of float4 elements
    const int threads = 256;
    const int per_block = threads * VPT;   // float4s per block

    if (n4 > 0) {
        int blocks = (n4 + per_block - 1) / per_block;
        FPQuantizer_76312978915927_kernel<<<blocks, threads>>>(
            (const float4*)x, (float4*)out, n4);
    }
    int tail_start = n4 << 2;
    int tail = n - tail_start;
    if (tail > 0) {
        FPQuantizer_tail_kernel<<<1, 128>>>(x, out, tail_start, n);
    }
}